// round 2
// baseline (speedup 1.0000x reference)
#include <cuda_runtime.h>
#include <cuda_bf16.h>
#include <stdint.h>

// Problem constants (match reference)
#define USER_NUM 100000
#define ITEM_NUM 100000
#define N_NODES  (USER_NUM + ITEM_NUM)
#define EMB      64
#define N_EDGES  6400000
#define N_LAYERS 3
#define EPS_F    0.1f

// Scratch: double-buffered ego embeddings. 2 * 200000 * 64 * 4B = 102.4 MB.
__device__ float g_ego_a[(size_t)N_NODES * EMB];
__device__ float g_ego_b[(size_t)N_NODES * EMB];

// ---------------------------------------------------------------------------
// SPMM: out[row] += val * x[col], scatter with vector atomics.
// 16 threads per edge, each thread handles one float4 (16B) of the 256B row.
// NOTE: adj indices are int32 (JAX silently downgrades int64 without x64).
// ---------------------------------------------------------------------------
__global__ void __launch_bounds__(256) spmm_kernel(
    const int* __restrict__ rows,
    const int* __restrict__ cols,
    const float* __restrict__ vals,
    const float* __restrict__ x,
    float* __restrict__ out)
{
    unsigned gid = blockIdx.x * 256u + threadIdx.x;
    unsigned e = gid >> 4;           // edge index
    unsigned t = gid & 15u;          // float4 slot within the 64-float row
    if (e >= N_EDGES) return;

    int r = rows[e];
    int c = cols[e];
    float v = vals[e];

    const float4* xp = reinterpret_cast<const float4*>(x + (size_t)c * EMB) + t;
    float4 xv = *xp;
    float4 p;
    p.x = xv.x * v; p.y = xv.y * v; p.z = xv.z * v; p.w = xv.w * v;

    float* op = out + (size_t)r * EMB + t * 4;
    asm volatile("red.global.add.v4.f32 [%0], {%1, %2, %3, %4};"
                 :: "l"(op), "f"(p.x), "f"(p.y), "f"(p.z), "f"(p.w)
                 : "memory");
}

// ---------------------------------------------------------------------------
// Perturb + accumulate. One warp per node, 2 floats (float2) per lane.
//   ego += sign(ego) * (noise / max(||noise||, 1e-12)) * EPS
// MODE 0 (k=0): final = ego ; cl = ego ; store ego back (needed by next layer)
// MODE 1 (k=1): final += ego ; store ego back
// MODE 2 (k=2): final = (final + ego) / 3 ; no ego store needed
// ---------------------------------------------------------------------------
template <int MODE>
__global__ void __launch_bounds__(256) perturb_kernel(
    float* __restrict__ ego,
    const float* __restrict__ noise_k,
    float* __restrict__ final_out,
    float* __restrict__ cl_out)
{
    unsigned node = (blockIdx.x * 256u + threadIdx.x) >> 5;
    unsigned lane = threadIdx.x & 31u;
    if (node >= N_NODES) return;

    size_t f2_idx = (size_t)node * 32 + lane;   // float2 index into [N,64]

    float2 nv = reinterpret_cast<const float2*>(noise_k)[f2_idx];
    float ss = nv.x * nv.x + nv.y * nv.y;
    #pragma unroll
    for (int o = 16; o > 0; o >>= 1)
        ss += __shfl_xor_sync(0xffffffffu, ss, o);

    float nrm = fmaxf(sqrtf(ss), 1e-12f);
    float f = EPS_F / nrm;

    float2* ep = reinterpret_cast<float2*>(ego) + f2_idx;
    float2 e = *ep;
    float sx = (e.x > 0.f) ? 1.f : ((e.x < 0.f) ? -1.f : 0.f);
    float sy = (e.y > 0.f) ? 1.f : ((e.y < 0.f) ? -1.f : 0.f);
    e.x += sx * nv.x * f;
    e.y += sy * nv.y * f;

    if (MODE != 2) *ep = e;  // next layer reads ego

    float2* fo = reinterpret_cast<float2*>(final_out) + f2_idx;
    if (MODE == 0) {
        *fo = e;
        reinterpret_cast<float2*>(cl_out)[f2_idx] = e;
    } else if (MODE == 1) {
        float2 a = *fo;
        a.x += e.x; a.y += e.y;
        *fo = a;
    } else {
        float2 a = *fo;
        const float inv3 = 1.0f / 3.0f;
        a.x = (a.x + e.x) * inv3;
        a.y = (a.y + e.y) * inv3;
        *fo = a;
    }
}

extern "C" void kernel_launch(void* const* d_in, const int* in_sizes, int n_in,
                              void* d_out, int out_size)
{
    const float* user_emb = (const float*)d_in[0];
    const float* item_emb = (const float*)d_in[1];
    const int*   adj_rows = (const int*)d_in[2];
    const int*   adj_cols = (const int*)d_in[3];
    const float* adj_vals = (const float*)d_in[4];
    const float* noise    = (const float*)d_in[5];

    float* out_final = (float*)d_out;                           // [N_NODES, EMB]
    float* out_cl    = (float*)d_out + (size_t)N_NODES * EMB;   // [N_NODES, EMB]

    float *bufA = nullptr, *bufB = nullptr;
    cudaGetSymbolAddress((void**)&bufA, g_ego_a);
    cudaGetSymbolAddress((void**)&bufB, g_ego_b);

    const size_t node_bytes = (size_t)N_NODES * EMB * sizeof(float);

    // ego0 = concat(user_emb, item_emb) into bufA
    cudaMemcpyAsync(bufA, user_emb, (size_t)USER_NUM * EMB * sizeof(float),
                    cudaMemcpyDeviceToDevice);
    cudaMemcpyAsync(bufA + (size_t)USER_NUM * EMB, item_emb,
                    (size_t)ITEM_NUM * EMB * sizeof(float),
                    cudaMemcpyDeviceToDevice);

    const unsigned spmm_blocks = (unsigned)(((size_t)N_EDGES * 16 + 255) / 256);
    const unsigned pert_blocks = (unsigned)(((size_t)N_NODES * 32 + 255) / 256);

    float* src = bufA;
    float* dst = bufB;

    for (int k = 0; k < N_LAYERS; k++) {
        cudaMemsetAsync(dst, 0, node_bytes);
        spmm_kernel<<<spmm_blocks, 256>>>(adj_rows, adj_cols, adj_vals, src, dst);
        const float* nk = noise + (size_t)k * N_NODES * EMB;
        if (k == 0)
            perturb_kernel<0><<<pert_blocks, 256>>>(dst, nk, out_final, out_cl);
        else if (k == 1)
            perturb_kernel<1><<<pert_blocks, 256>>>(dst, nk, out_final, out_cl);
        else
            perturb_kernel<2><<<pert_blocks, 256>>>(dst, nk, out_final, out_cl);
        float* tmp = src; src = dst; dst = tmp;
    }
}

// round 3
// speedup vs baseline: 2.0961x; 2.0961x over previous
#include <cuda_runtime.h>
#include <cuda_bf16.h>
#include <stdint.h>

#define USER_NUM 100000
#define ITEM_NUM 100000
#define N_NODES  (USER_NUM + ITEM_NUM)
#define EMB      64
#define N_EDGES  6400000
#define N_LAYERS 3
#define EPS_F    0.1f

// Scratch (__device__ globals: no allocation allowed)
__device__ float g_ego_a[(size_t)N_NODES * EMB];   // 51.2 MB
__device__ float g_ego_b[(size_t)N_NODES * EMB];   // 51.2 MB
__device__ int2  g_perm[(size_t)N_EDGES];          // {col, val_bits} 51.2 MB
__device__ int   g_counts[N_NODES];
__device__ int   g_start[N_NODES];
__device__ int   g_cursor[N_NODES];
__device__ int   g_total;

// ---------------------------------------------------------------------------
// Pass 1: histogram of destination rows
// ---------------------------------------------------------------------------
__global__ void __launch_bounds__(256) hist_kernel(const int* __restrict__ rows)
{
    unsigned e = blockIdx.x * 256u + threadIdx.x;
    if (e < N_EDGES)
        atomicAdd(&g_counts[rows[e]], 1);
}

// ---------------------------------------------------------------------------
// Pass 2: assign contiguous segment starts (order arbitrary).
// Warp-aggregated: one atomicAdd on g_total per warp, prefix via warp scan.
// ---------------------------------------------------------------------------
__global__ void __launch_bounds__(256) assign_kernel()
{
    unsigned r = blockIdx.x * 256u + threadIdx.x;
    unsigned lane = threadIdx.x & 31u;

    int c = (r < N_NODES) ? g_counts[r] : 0;

    // inclusive warp scan of c
    int incl = c;
    #pragma unroll
    for (int o = 1; o < 32; o <<= 1) {
        int n = __shfl_up_sync(0xffffffffu, incl, o);
        if (lane >= (unsigned)o) incl += n;
    }
    int excl = incl - c;

    int base = 0;
    if (lane == 31) base = atomicAdd(&g_total, incl);
    base = __shfl_sync(0xffffffffu, base, 31);

    if (r < N_NODES) {
        int s = base + excl;
        g_start[r]  = s;
        g_cursor[r] = s;
    }
}

// ---------------------------------------------------------------------------
// Pass 3: scatter {col, val} into per-row contiguous segments
// ---------------------------------------------------------------------------
__global__ void __launch_bounds__(256) scatter_kernel(
    const int* __restrict__ rows,
    const int* __restrict__ cols,
    const float* __restrict__ vals)
{
    unsigned e = blockIdx.x * 256u + threadIdx.x;
    if (e >= N_EDGES) return;
    int r = rows[e];
    int p = atomicAdd(&g_cursor[r], 1);
    g_perm[p] = make_int2(cols[e], __float_as_int(vals[e]));
}

// ---------------------------------------------------------------------------
// Fused CSR-gather SPMM + perturb + accumulate. One warp per output row.
// Each lane owns 2 consecutive floats (float2) of the 64-wide row.
// MODE 0: final = ego ; cl = ego ; store ego
// MODE 1: final += ego ; store ego
// MODE 2: final = (final + ego)/3 ; no ego store
// ---------------------------------------------------------------------------
template <int MODE>
__global__ void __launch_bounds__(256) spmm_perturb_kernel(
    const float* __restrict__ x,
    float* __restrict__ ego_dst,
    const float* __restrict__ noise_k,
    float* __restrict__ final_out,
    float* __restrict__ cl_out)
{
    __shared__ int2 scv[8][32];

    unsigned warp = threadIdx.x >> 5;
    unsigned lane = threadIdx.x & 31u;
    unsigned r = blockIdx.x * 8u + warp;
    if (r >= N_NODES) return;

    int s   = g_start[r];
    int deg = g_counts[r];

    float acc0 = 0.f, acc1 = 0.f;

    for (int base = 0; base < deg; base += 32) {
        int idx = base + (int)lane;
        int2 cv = (idx < deg) ? g_perm[s + idx] : make_int2(0, 0);
        scv[warp][lane] = cv;
        __syncwarp();
        int cnt = min(32, deg - base);
        #pragma unroll 8
        for (int j = 0; j < cnt; j++) {
            int2 cvj = scv[warp][j];
            float vj = __int_as_float(cvj.y);
            float2 xv = __ldg(reinterpret_cast<const float2*>(
                                  x + (size_t)cvj.x * EMB) + lane);
            acc0 = fmaf(vj, xv.x, acc0);
            acc1 = fmaf(vj, xv.y, acc1);
        }
        __syncwarp();
    }

    // Perturb: ego += sign(ego) * (noise / max(||noise||,1e-12)) * EPS
    size_t f2_idx = (size_t)r * 32 + lane;
    float2 nv = reinterpret_cast<const float2*>(noise_k)[f2_idx];
    float ss = nv.x * nv.x + nv.y * nv.y;
    #pragma unroll
    for (int o = 16; o > 0; o >>= 1)
        ss += __shfl_xor_sync(0xffffffffu, ss, o);
    float f = EPS_F / fmaxf(sqrtf(ss), 1e-12f);

    float sx = (acc0 > 0.f) ? 1.f : ((acc0 < 0.f) ? -1.f : 0.f);
    float sy = (acc1 > 0.f) ? 1.f : ((acc1 < 0.f) ? -1.f : 0.f);
    float2 e;
    e.x = fmaf(sx * nv.x, f, acc0);
    e.y = fmaf(sy * nv.y, f, acc1);

    if (MODE != 2)
        reinterpret_cast<float2*>(ego_dst)[f2_idx] = e;

    float2* fo = reinterpret_cast<float2*>(final_out) + f2_idx;
    if (MODE == 0) {
        *fo = e;
        reinterpret_cast<float2*>(cl_out)[f2_idx] = e;
    } else if (MODE == 1) {
        float2 a = *fo;
        a.x += e.x; a.y += e.y;
        *fo = a;
    } else {
        float2 a = *fo;
        const float inv3 = 1.0f / 3.0f;
        a.x = (a.x + e.x) * inv3;
        a.y = (a.y + e.y) * inv3;
        *fo = a;
    }
}

extern "C" void kernel_launch(void* const* d_in, const int* in_sizes, int n_in,
                              void* d_out, int out_size)
{
    const float* user_emb = (const float*)d_in[0];
    const float* item_emb = (const float*)d_in[1];
    const int*   adj_rows = (const int*)d_in[2];
    const int*   adj_cols = (const int*)d_in[3];
    const float* adj_vals = (const float*)d_in[4];
    const float* noise    = (const float*)d_in[5];

    float* out_final = (float*)d_out;
    float* out_cl    = (float*)d_out + (size_t)N_NODES * EMB;

    float *bufA = nullptr, *bufB = nullptr;
    int *counts_p = nullptr, *total_p = nullptr;
    cudaGetSymbolAddress((void**)&bufA, g_ego_a);
    cudaGetSymbolAddress((void**)&bufB, g_ego_b);
    cudaGetSymbolAddress((void**)&counts_p, g_counts);
    cudaGetSymbolAddress((void**)&total_p, g_total);

    // Zero histogram + global cursor
    cudaMemsetAsync(counts_p, 0, (size_t)N_NODES * sizeof(int));
    cudaMemsetAsync(total_p, 0, sizeof(int));

    const unsigned edge_blocks = (N_EDGES + 255) / 256;
    const unsigned node_blocks = (N_NODES + 255) / 256;

    // CSR build
    hist_kernel<<<edge_blocks, 256>>>(adj_rows);
    assign_kernel<<<node_blocks, 256>>>();
    scatter_kernel<<<edge_blocks, 256>>>(adj_rows, adj_cols, adj_vals);

    // ego0 = concat(user_emb, item_emb)
    cudaMemcpyAsync(bufA, user_emb, (size_t)USER_NUM * EMB * sizeof(float),
                    cudaMemcpyDeviceToDevice);
    cudaMemcpyAsync(bufA + (size_t)USER_NUM * EMB, item_emb,
                    (size_t)ITEM_NUM * EMB * sizeof(float),
                    cudaMemcpyDeviceToDevice);

    const unsigned spmm_blocks = (N_NODES + 7) / 8;   // 8 warps/block, 1 row/warp

    spmm_perturb_kernel<0><<<spmm_blocks, 256>>>(bufA, bufB,
        noise + (size_t)0 * N_NODES * EMB, out_final, out_cl);
    spmm_perturb_kernel<1><<<spmm_blocks, 256>>>(bufB, bufA,
        noise + (size_t)1 * N_NODES * EMB, out_final, out_cl);
    spmm_perturb_kernel<2><<<spmm_blocks, 256>>>(bufA, bufB,
        noise + (size_t)2 * N_NODES * EMB, out_final, out_cl);
}

// round 4
// speedup vs baseline: 2.5510x; 1.2170x over previous
#include <cuda_runtime.h>
#include <cuda_bf16.h>
#include <stdint.h>

#define USER_NUM 100000
#define ITEM_NUM 100000
#define N_NODES  (USER_NUM + ITEM_NUM)
#define EMB      64
#define N_EDGES  6400000
#define N_LAYERS 3
#define EPS_F    0.1f

// Scratch (__device__ globals: no allocation allowed)
__device__ float g_ego_a[(size_t)N_NODES * EMB];   // 51.2 MB
__device__ float g_ego_b[(size_t)N_NODES * EMB];   // 51.2 MB
__device__ int2  g_perm[(size_t)N_EDGES];          // {col, val_bits} 51.2 MB
__device__ int   g_counts[N_NODES];
__device__ int   g_start[N_NODES];
__device__ int   g_cursor[N_NODES];
__device__ int   g_total;

// ---------------------------------------------------------------------------
// Pass 1: histogram of destination rows
// ---------------------------------------------------------------------------
__global__ void __launch_bounds__(256) hist_kernel(const int* __restrict__ rows)
{
    unsigned e = blockIdx.x * 256u + threadIdx.x;
    if (e < N_EDGES)
        atomicAdd(&g_counts[rows[e]], 1);
}

// ---------------------------------------------------------------------------
// Pass 2: assign contiguous segment starts (order arbitrary).
// ---------------------------------------------------------------------------
__global__ void __launch_bounds__(256) assign_kernel()
{
    unsigned r = blockIdx.x * 256u + threadIdx.x;
    unsigned lane = threadIdx.x & 31u;

    int c = (r < N_NODES) ? g_counts[r] : 0;

    int incl = c;
    #pragma unroll
    for (int o = 1; o < 32; o <<= 1) {
        int n = __shfl_up_sync(0xffffffffu, incl, o);
        if (lane >= (unsigned)o) incl += n;
    }
    int excl = incl - c;

    int base = 0;
    if (lane == 31) base = atomicAdd(&g_total, incl);
    base = __shfl_sync(0xffffffffu, base, 31);

    if (r < N_NODES) {
        int s = base + excl;
        g_start[r]  = s;
        g_cursor[r] = s;
    }
}

// ---------------------------------------------------------------------------
// Pass 3: scatter {col, val} into per-row contiguous segments
// ---------------------------------------------------------------------------
__global__ void __launch_bounds__(256) scatter_kernel(
    const int* __restrict__ rows,
    const int* __restrict__ cols,
    const float* __restrict__ vals)
{
    unsigned e = blockIdx.x * 256u + threadIdx.x;
    if (e >= N_EDGES) return;
    int r = rows[e];
    int p = atomicAdd(&g_cursor[r], 1);
    g_perm[p] = make_int2(cols[e], __float_as_int(vals[e]));
}

// ---------------------------------------------------------------------------
// Fused CSR-gather SPMM + perturb + accumulate.
// TWO rows per warp: lanes 0-15 own row r0, lanes 16-31 own row r1.
// Each lane holds one float4 (16B) of its row (16 lanes x 16B = 256B row).
// One LDG.128 instruction gathers for BOTH rows (one edge each).
// Inner loop batches 4 independent gathers to raise MLP.
// MODE 0: final = ego ; cl = ego ; store ego
// MODE 1: final += ego ; store ego
// MODE 2: final = (final + ego)/3 ; no ego store
// ---------------------------------------------------------------------------
template <int MODE>
__global__ void __launch_bounds__(256) spmm_perturb_kernel(
    const float* __restrict__ x,
    float* __restrict__ ego_dst,
    const float* __restrict__ noise_k,
    float* __restrict__ final_out,
    float* __restrict__ cl_out)
{
    __shared__ int2 scv[8][32];

    const unsigned warp = threadIdx.x >> 5;
    const unsigned lane = threadIdx.x & 31u;
    const unsigned sub  = lane & 15u;         // float4 slot within row
    const unsigned half = lane & 16u;         // 0 = row0, 16 = row1

    unsigned r = blockIdx.x * 16u + warp * 2u + (half >> 4);
    if (r >= N_NODES) return;

    const int s   = g_start[r];
    const int deg = g_counts[r];
    const int degmax = max(deg, __shfl_xor_sync(0xffffffffu, deg, 16));

    float4 acc = make_float4(0.f, 0.f, 0.f, 0.f);

    const float4* __restrict__ x4 = reinterpret_cast<const float4*>(x);

    for (int base = 0; base < degmax; base += 16) {
        int idx = base + (int)sub;
        int2 cv = (idx < deg) ? g_perm[s + idx] : make_int2(0, 0);
        scv[warp][lane] = cv;
        __syncwarp();

        #pragma unroll
        for (int j = 0; j < 16; j += 4) {
            int2 c0 = scv[warp][half + j + 0];
            int2 c1 = scv[warp][half + j + 1];
            int2 c2 = scv[warp][half + j + 2];
            int2 c3 = scv[warp][half + j + 3];
            float4 x0 = __ldg(x4 + (size_t)c0.x * 16 + sub);
            float4 x1 = __ldg(x4 + (size_t)c1.x * 16 + sub);
            float4 x2 = __ldg(x4 + (size_t)c2.x * 16 + sub);
            float4 x3 = __ldg(x4 + (size_t)c3.x * 16 + sub);
            float v0 = __int_as_float(c0.y);
            float v1 = __int_as_float(c1.y);
            float v2 = __int_as_float(c2.y);
            float v3 = __int_as_float(c3.y);
            acc.x = fmaf(v0, x0.x, acc.x); acc.y = fmaf(v0, x0.y, acc.y);
            acc.z = fmaf(v0, x0.z, acc.z); acc.w = fmaf(v0, x0.w, acc.w);
            acc.x = fmaf(v1, x1.x, acc.x); acc.y = fmaf(v1, x1.y, acc.y);
            acc.z = fmaf(v1, x1.z, acc.z); acc.w = fmaf(v1, x1.w, acc.w);
            acc.x = fmaf(v2, x2.x, acc.x); acc.y = fmaf(v2, x2.y, acc.y);
            acc.z = fmaf(v2, x2.z, acc.z); acc.w = fmaf(v2, x2.w, acc.w);
            acc.x = fmaf(v3, x3.x, acc.x); acc.y = fmaf(v3, x3.y, acc.y);
            acc.z = fmaf(v3, x3.z, acc.z); acc.w = fmaf(v3, x3.w, acc.w);
        }
        __syncwarp();
    }

    // Perturb: ego += sign(ego) * (noise / max(||noise||,1e-12)) * EPS
    size_t f4_idx = (size_t)r * 16 + sub;     // float4 index into [N,64]
    float4 nv = __ldg(reinterpret_cast<const float4*>(noise_k) + f4_idx);
    float ss = nv.x * nv.x + nv.y * nv.y + nv.z * nv.z + nv.w * nv.w;
    #pragma unroll
    for (int o = 8; o > 0; o >>= 1)           // reduce within 16-lane half
        ss += __shfl_xor_sync(0xffffffffu, ss, o);
    float f = EPS_F / fmaxf(sqrtf(ss), 1e-12f);

    float4 e;
    {
        float sx = (acc.x > 0.f) ? 1.f : ((acc.x < 0.f) ? -1.f : 0.f);
        float sy = (acc.y > 0.f) ? 1.f : ((acc.y < 0.f) ? -1.f : 0.f);
        float sz = (acc.z > 0.f) ? 1.f : ((acc.z < 0.f) ? -1.f : 0.f);
        float sw = (acc.w > 0.f) ? 1.f : ((acc.w < 0.f) ? -1.f : 0.f);
        e.x = fmaf(sx * nv.x, f, acc.x);
        e.y = fmaf(sy * nv.y, f, acc.y);
        e.z = fmaf(sz * nv.z, f, acc.z);
        e.w = fmaf(sw * nv.w, f, acc.w);
    }

    if (MODE != 2)
        reinterpret_cast<float4*>(ego_dst)[f4_idx] = e;

    float4* fo = reinterpret_cast<float4*>(final_out) + f4_idx;
    if (MODE == 0) {
        *fo = e;
        reinterpret_cast<float4*>(cl_out)[f4_idx] = e;
    } else if (MODE == 1) {
        float4 a = *fo;
        a.x += e.x; a.y += e.y; a.z += e.z; a.w += e.w;
        *fo = a;
    } else {
        float4 a = *fo;
        const float inv3 = 1.0f / 3.0f;
        a.x = (a.x + e.x) * inv3;
        a.y = (a.y + e.y) * inv3;
        a.z = (a.z + e.z) * inv3;
        a.w = (a.w + e.w) * inv3;
        *fo = a;
    }
}

extern "C" void kernel_launch(void* const* d_in, const int* in_sizes, int n_in,
                              void* d_out, int out_size)
{
    const float* user_emb = (const float*)d_in[0];
    const float* item_emb = (const float*)d_in[1];
    const int*   adj_rows = (const int*)d_in[2];
    const int*   adj_cols = (const int*)d_in[3];
    const float* adj_vals = (const float*)d_in[4];
    const float* noise    = (const float*)d_in[5];

    float* out_final = (float*)d_out;
    float* out_cl    = (float*)d_out + (size_t)N_NODES * EMB;

    float *bufA = nullptr, *bufB = nullptr;
    int *counts_p = nullptr, *total_p = nullptr;
    cudaGetSymbolAddress((void**)&bufA, g_ego_a);
    cudaGetSymbolAddress((void**)&bufB, g_ego_b);
    cudaGetSymbolAddress((void**)&counts_p, g_counts);
    cudaGetSymbolAddress((void**)&total_p, g_total);

    cudaMemsetAsync(counts_p, 0, (size_t)N_NODES * sizeof(int));
    cudaMemsetAsync(total_p, 0, sizeof(int));

    const unsigned edge_blocks = (N_EDGES + 255) / 256;
    const unsigned node_blocks = (N_NODES + 255) / 256;

    hist_kernel<<<edge_blocks, 256>>>(adj_rows);
    assign_kernel<<<node_blocks, 256>>>();
    scatter_kernel<<<edge_blocks, 256>>>(adj_rows, adj_cols, adj_vals);

    cudaMemcpyAsync(bufA, user_emb, (size_t)USER_NUM * EMB * sizeof(float),
                    cudaMemcpyDeviceToDevice);
    cudaMemcpyAsync(bufA + (size_t)USER_NUM * EMB, item_emb,
                    (size_t)ITEM_NUM * EMB * sizeof(float),
                    cudaMemcpyDeviceToDevice);

    const unsigned spmm_blocks = (N_NODES + 15) / 16;  // 8 warps/block, 2 rows/warp

    spmm_perturb_kernel<0><<<spmm_blocks, 256>>>(bufA, bufB,
        noise + (size_t)0 * N_NODES * EMB, out_final, out_cl);
    spmm_perturb_kernel<1><<<spmm_blocks, 256>>>(bufB, bufA,
        noise + (size_t)1 * N_NODES * EMB, out_final, out_cl);
    spmm_perturb_kernel<2><<<spmm_blocks, 256>>>(bufA, bufB,
        noise + (size_t)2 * N_NODES * EMB, out_final, out_cl);
}